// round 1
// baseline (speedup 1.0000x reference)
#include <cuda_runtime.h>
#include <cstdint>
#include <cstddef>

// Problem constants
#define TSEQ   2048
#define CDIM   1024
#define NBATCH 2
#define NHEAD  16
#define HDIM   64
#define NBH    (NBATCH * NHEAD)       // 32
#define ROWS_TOT (NBATCH * TSEQ)      // 4096
#define QK_SCALE 0.125f               // 1/sqrt(64)

// ---------------------------------------------------------------------------
// Scratch (device globals: the sanctioned allocation-free scratch mechanism)
// ---------------------------------------------------------------------------
__device__ float g_q[(size_t)ROWS_TOT * CDIM];           // 16 MB
__device__ float g_k[(size_t)ROWS_TOT * CDIM];           // 16 MB
__device__ float g_v[(size_t)ROWS_TOT * CDIM];           // 16 MB
__device__ float g_o[(size_t)ROWS_TOT * CDIM];           // 16 MB
__device__ float g_att[(size_t)NBH * TSEQ * TSEQ];       // 512 MB (scores / probs)
__device__ float g_rsum[(size_t)NBH * TSEQ];             // softmax row sums

// ---------------------------------------------------------------------------
// Helpers
// ---------------------------------------------------------------------------
__device__ __forceinline__ float tf32r(float x) {
    unsigned u;
    asm("cvt.rna.tf32.f32 %0, %1;" : "=r"(u) : "f"(x));
    return __uint_as_float(u);
}

// m16n8k8 tf32 MMA, fp32 accumulate. Standard fragment layout:
//  A: a0(r=g,c=t) a1(r=g+8,c=t) a2(r=g,c=t+4) a3(r=g+8,c=t+4)
//  B: b0(k=t,n=g) b1(k=t+4,n=g)
//  C: c0(r=g,c=2t) c1(..2t+1) c2(r=g+8,c=2t) c3(..2t+1)     [g=lane>>2, t=lane&3]
__device__ __forceinline__ void mma8(float* c,
    unsigned a0, unsigned a1, unsigned a2, unsigned a3,
    unsigned b0, unsigned b1)
{
    asm volatile(
        "mma.sync.aligned.m16n8k8.row.col.f32.tf32.tf32.f32 "
        "{%0,%1,%2,%3},{%4,%5,%6,%7},{%8,%9},{%0,%1,%2,%3};\n"
        : "+f"(c[0]), "+f"(c[1]), "+f"(c[2]), "+f"(c[3])
        : "r"(a0), "r"(a1), "r"(a2), "r"(a3), "r"(b0), "r"(b1));
}

// ---------------------------------------------------------------------------
// NT GEMM: C[M,N] = A[M,K] * B[N,K]^T   (both row-major, K contiguous)
// Block tile 128x64, 8 warps (4 M x 2 N), warp tile 32x32, K-tile 16.
// SPLIT=true: 2-term tf32 split (3 MMAs) for near-fp32 accuracy.
// ---------------------------------------------------------------------------
template <bool SPLIT>
__global__ void __launch_bounds__(256)
gemm_nt(const float* __restrict__ A, const float* __restrict__ B,
        float* __restrict__ C, int M, int N, int K)
{
    __shared__ float Ah[128][20];
    __shared__ float Bh[64][20];
    __shared__ float Al[SPLIT ? 128 : 1][20];
    __shared__ float Bl[SPLIT ? 64 : 1][20];

    const int t    = threadIdx.x;
    const int bm   = blockIdx.y * 128;
    const int bn   = blockIdx.x * 64;
    const int w    = t >> 5;
    const int lane = t & 31;
    const int g    = lane >> 2;
    const int tg   = lane & 3;
    const int wm   = w & 3;   // 0..3  (M direction)
    const int wn   = w >> 2;  // 0..1  (N direction)

    float acc[2][4][4];
    #pragma unroll
    for (int mt = 0; mt < 2; mt++)
        #pragma unroll
        for (int nt = 0; nt < 4; nt++)
            #pragma unroll
            for (int r = 0; r < 4; r++)
                acc[mt][nt][r] = 0.f;

    for (int kt = 0; kt < K; kt += 16) {
        // Stage A tile (128 x 16) with tf32 split conversion
        #pragma unroll
        for (int i = 0; i < 2; i++) {
            int idx = t + i * 256;          // float4 index, 0..511
            int r   = idx >> 2;
            int c   = (idx & 3) * 4;
            float4 va = *(const float4*)(A + (size_t)(bm + r) * K + kt + c);
            float h0 = tf32r(va.x), h1 = tf32r(va.y), h2 = tf32r(va.z), h3 = tf32r(va.w);
            *(float4*)&Ah[r][c] = make_float4(h0, h1, h2, h3);
            if (SPLIT)
                *(float4*)&Al[r][c] = make_float4(tf32r(va.x - h0), tf32r(va.y - h1),
                                                  tf32r(va.z - h2), tf32r(va.w - h3));
        }
        // Stage B tile (64 x 16)
        {
            int r = t >> 2;
            int c = (t & 3) * 4;
            float4 vb = *(const float4*)(B + (size_t)(bn + r) * K + kt + c);
            float h0 = tf32r(vb.x), h1 = tf32r(vb.y), h2 = tf32r(vb.z), h3 = tf32r(vb.w);
            *(float4*)&Bh[r][c] = make_float4(h0, h1, h2, h3);
            if (SPLIT)
                *(float4*)&Bl[r][c] = make_float4(tf32r(vb.x - h0), tf32r(vb.y - h1),
                                                  tf32r(vb.z - h2), tf32r(vb.w - h3));
        }
        __syncthreads();

        #pragma unroll
        for (int ks = 0; ks < 2; ks++) {
            const int k0 = ks * 8;
            unsigned a0[2], a1[2], a2[2], a3[2];
            unsigned p0[2], p1[2], p2[2], p3[2];
            #pragma unroll
            for (int mt = 0; mt < 2; mt++) {
                int r = wm * 32 + mt * 16 + g;
                a0[mt] = __float_as_uint(Ah[r    ][k0 + tg    ]);
                a1[mt] = __float_as_uint(Ah[r + 8][k0 + tg    ]);
                a2[mt] = __float_as_uint(Ah[r    ][k0 + tg + 4]);
                a3[mt] = __float_as_uint(Ah[r + 8][k0 + tg + 4]);
                if (SPLIT) {
                    p0[mt] = __float_as_uint(Al[r    ][k0 + tg    ]);
                    p1[mt] = __float_as_uint(Al[r + 8][k0 + tg    ]);
                    p2[mt] = __float_as_uint(Al[r    ][k0 + tg + 4]);
                    p3[mt] = __float_as_uint(Al[r + 8][k0 + tg + 4]);
                }
            }
            #pragma unroll
            for (int nt = 0; nt < 4; nt++) {
                int cn = wn * 32 + nt * 8 + g;
                unsigned b0 = __float_as_uint(Bh[cn][k0 + tg    ]);
                unsigned b1 = __float_as_uint(Bh[cn][k0 + tg + 4]);
                unsigned q0 = 0, q1 = 0;
                if (SPLIT) {
                    q0 = __float_as_uint(Bl[cn][k0 + tg    ]);
                    q1 = __float_as_uint(Bl[cn][k0 + tg + 4]);
                }
                #pragma unroll
                for (int mt = 0; mt < 2; mt++) {
                    mma8(acc[mt][nt], a0[mt], a1[mt], a2[mt], a3[mt], b0, b1);
                    if (SPLIT) {
                        mma8(acc[mt][nt], p0[mt], p1[mt], p2[mt], p3[mt], b0, b1);
                        mma8(acc[mt][nt], a0[mt], a1[mt], a2[mt], a3[mt], q0, q1);
                    }
                }
            }
        }
        __syncthreads();
    }

    #pragma unroll
    for (int mt = 0; mt < 2; mt++) {
        #pragma unroll
        for (int nt = 0; nt < 4; nt++) {
            int r = bm + wm * 32 + mt * 16 + g;
            int c = bn + wn * 32 + nt * 8 + 2 * tg;
            C[(size_t)r * N + c]           = acc[mt][nt][0];
            C[(size_t)r * N + c + 1]       = acc[mt][nt][1];
            C[(size_t)(r + 8) * N + c]     = acc[mt][nt][2];
            C[(size_t)(r + 8) * N + c + 1] = acc[mt][nt][3];
        }
    }
}

// ---------------------------------------------------------------------------
// Scores: S[bh, i, j] = scale * q_i . k_j, causal tile skipping.
// 64x64 tile per block, 128 threads (4 warps x 16 rows). Masked (j>i) -> 0
// so the PV GEMM can consume full tiles (softmax only reads j<=i).
// ---------------------------------------------------------------------------
__global__ void __launch_bounds__(128) scores_kernel()
{
    const int jt = blockIdx.x, it = blockIdx.y, bh = blockIdx.z;
    if (jt > it) return;
    const int b = bh >> 4, h = bh & 15;

    __shared__ float Qs[64][68];
    __shared__ float Ks[64][68];

    const int t = threadIdx.x;
    const float* qb = g_q + (size_t)(b * TSEQ + it * 64) * CDIM + h * 64;
    const float* kb = g_k + (size_t)(b * TSEQ + jt * 64) * CDIM + h * 64;

    #pragma unroll
    for (int i = 0; i < 8; i++) {
        int idx = t + i * 128;
        int r   = idx >> 4;
        int c   = (idx & 15) * 4;
        float4 q4 = *(const float4*)(qb + (size_t)r * CDIM + c);
        *(float4*)&Qs[r][c] = make_float4(tf32r(q4.x * QK_SCALE), tf32r(q4.y * QK_SCALE),
                                          tf32r(q4.z * QK_SCALE), tf32r(q4.w * QK_SCALE));
        float4 k4 = *(const float4*)(kb + (size_t)r * CDIM + c);
        *(float4*)&Ks[r][c] = make_float4(tf32r(k4.x), tf32r(k4.y), tf32r(k4.z), tf32r(k4.w));
    }
    __syncthreads();

    const int w = t >> 5, lane = t & 31, g = lane >> 2, tg = lane & 3;
    float acc[8][4];
    #pragma unroll
    for (int nt = 0; nt < 8; nt++)
        #pragma unroll
        for (int r = 0; r < 4; r++) acc[nt][r] = 0.f;

    #pragma unroll
    for (int ks = 0; ks < 8; ks++) {
        const int k0 = ks * 8;
        const int r  = w * 16 + g;
        unsigned a0 = __float_as_uint(Qs[r    ][k0 + tg    ]);
        unsigned a1 = __float_as_uint(Qs[r + 8][k0 + tg    ]);
        unsigned a2 = __float_as_uint(Qs[r    ][k0 + tg + 4]);
        unsigned a3 = __float_as_uint(Qs[r + 8][k0 + tg + 4]);
        #pragma unroll
        for (int nt = 0; nt < 8; nt++) {
            unsigned b0 = __float_as_uint(Ks[nt * 8 + g][k0 + tg    ]);
            unsigned b1 = __float_as_uint(Ks[nt * 8 + g][k0 + tg + 4]);
            mma8(acc[nt], a0, a1, a2, a3, b0, b1);
        }
    }

    float* Sout = g_att + ((size_t)bh * TSEQ + (size_t)it * 64) * TSEQ + (size_t)jt * 64;
    const bool diag = (it == jt);
    #pragma unroll
    for (int nt = 0; nt < 8; nt++) {
        int r = w * 16 + g;
        int c = nt * 8 + 2 * tg;
        float v0 = acc[nt][0], v1 = acc[nt][1], v2 = acc[nt][2], v3 = acc[nt][3];
        if (diag) {
            if (c     > r)     v0 = 0.f;
            if (c + 1 > r)     v1 = 0.f;
            if (c     > r + 8) v2 = 0.f;
            if (c + 1 > r + 8) v3 = 0.f;
        }
        Sout[(size_t)r * TSEQ + c]           = v0;
        Sout[(size_t)r * TSEQ + c + 1]       = v1;
        Sout[(size_t)(r + 8) * TSEQ + c]     = v2;
        Sout[(size_t)(r + 8) * TSEQ + c + 1] = v3;
    }
}

// ---------------------------------------------------------------------------
// Row softmax over j in [0, i]. Stores UNNORMALIZED exp(s - max) in place and
// the row sum in g_rsum (PV epilogue divides) — saves a full rescale pass.
// ---------------------------------------------------------------------------
__global__ void __launch_bounds__(128) softmax_kernel()
{
    __shared__ float red[128];
    const int bid = blockIdx.x;
    const int bh  = bid >> 11;
    const int i   = bid & 2047;
    float* row = g_att + ((size_t)bh * TSEQ + i) * TSEQ;
    const int len = i + 1;
    const int t   = threadIdx.x;

    float mx = -3.0e38f;
    for (int j = t; j < len; j += 128) mx = fmaxf(mx, row[j]);
    red[t] = mx;
    __syncthreads();
    #pragma unroll
    for (int s = 64; s > 0; s >>= 1) {
        if (t < s) red[t] = fmaxf(red[t], red[t + s]);
        __syncthreads();
    }
    mx = red[0];
    __syncthreads();

    float sum = 0.f;
    for (int j = t; j < len; j += 128) {
        float e = __expf(row[j] - mx);
        row[j] = e;
        sum += e;
    }
    red[t] = sum;
    __syncthreads();
    #pragma unroll
    for (int s = 64; s > 0; s >>= 1) {
        if (t < s) red[t] += red[t + s];
        __syncthreads();
    }
    if (t == 0) g_rsum[bid] = red[0];
}

// ---------------------------------------------------------------------------
// PV: O[i, d] = (1/rowsum_i) * sum_{j<=i} P[i,j] * V[j,d]
// Block = one 64-query tile of one (b,h). K-loop over j tiles 0..it.
// ---------------------------------------------------------------------------
__global__ void __launch_bounds__(128) pv_kernel()
{
    const int it = blockIdx.x, bh = blockIdx.y;
    const int b = bh >> 4, h = bh & 15;

    __shared__ float Ps[64][68];
    __shared__ float Vs[64][68];

    const int t = threadIdx.x, w = t >> 5, lane = t & 31, g = lane >> 2, tg = lane & 3;

    float acc[8][4];
    #pragma unroll
    for (int nt = 0; nt < 8; nt++)
        #pragma unroll
        for (int r = 0; r < 4; r++) acc[nt][r] = 0.f;

    const float* Prow = g_att + ((size_t)bh * TSEQ + (size_t)it * 64) * TSEQ;
    const float* vb   = g_v + (size_t)(b * TSEQ) * CDIM + h * 64;

    for (int jt = 0; jt <= it; jt++) {
        #pragma unroll
        for (int i = 0; i < 8; i++) {
            int idx = t + i * 128;
            int r   = idx >> 4;
            int c   = (idx & 15) * 4;
            float4 p4 = *(const float4*)(Prow + (size_t)r * TSEQ + jt * 64 + c);
            *(float4*)&Ps[r][c] = make_float4(tf32r(p4.x), tf32r(p4.y), tf32r(p4.z), tf32r(p4.w));
            float4 v4 = *(const float4*)(vb + (size_t)(jt * 64 + r) * CDIM + c);
            *(float4*)&Vs[r][c] = make_float4(tf32r(v4.x), tf32r(v4.y), tf32r(v4.z), tf32r(v4.w));
        }
        __syncthreads();

        #pragma unroll
        for (int ks = 0; ks < 8; ks++) {
            const int k0 = ks * 8;
            const int r  = w * 16 + g;
            unsigned a0 = __float_as_uint(Ps[r    ][k0 + tg    ]);
            unsigned a1 = __float_as_uint(Ps[r + 8][k0 + tg    ]);
            unsigned a2 = __float_as_uint(Ps[r    ][k0 + tg + 4]);
            unsigned a3 = __float_as_uint(Ps[r + 8][k0 + tg + 4]);
            #pragma unroll
            for (int nt = 0; nt < 8; nt++) {
                unsigned b0 = __float_as_uint(Vs[k0 + tg    ][nt * 8 + g]);
                unsigned b1 = __float_as_uint(Vs[k0 + tg + 4][nt * 8 + g]);
                mma8(acc[nt], a0, a1, a2, a3, b0, b1);
            }
        }
        __syncthreads();
    }

    const int r = w * 16 + g;
    const float inv0 = 1.f / g_rsum[(size_t)bh * TSEQ + it * 64 + r];
    const float inv1 = 1.f / g_rsum[(size_t)bh * TSEQ + it * 64 + r + 8];
    float* ob = g_o + (size_t)(b * TSEQ + it * 64) * CDIM + h * 64;
    #pragma unroll
    for (int nt = 0; nt < 8; nt++) {
        int c = nt * 8 + 2 * tg;
        ob[(size_t)r * CDIM + c]           = acc[nt][0] * inv0;
        ob[(size_t)r * CDIM + c + 1]       = acc[nt][1] * inv0;
        ob[(size_t)(r + 8) * CDIM + c]     = acc[nt][2] * inv1;
        ob[(size_t)(r + 8) * CDIM + c + 1] = acc[nt][3] * inv1;
    }
}

// ---------------------------------------------------------------------------
// Launch
// ---------------------------------------------------------------------------
extern "C" void kernel_launch(void* const* d_in, const int* in_sizes, int n_in,
                              void* d_out, int out_size)
{
    const float* x  = (const float*)d_in[0];
    const float* Wq = (const float*)d_in[1];
    const float* Wk = (const float*)d_in[2];
    const float* Wv = (const float*)d_in[3];
    const float* Wo = (const float*)d_in[4];
    float* out = (float*)d_out;

    float *q, *k, *v, *o;
    cudaGetSymbolAddress((void**)&q, g_q);
    cudaGetSymbolAddress((void**)&k, g_k);
    cudaGetSymbolAddress((void**)&v, g_v);
    cudaGetSymbolAddress((void**)&o, g_o);

    dim3 ggrid(CDIM / 64, ROWS_TOT / 128);   // (16, 32)

    // Projections: plain tf32 for Q,K (softmax tolerates ~2e-4 logit error),
    // split-tf32 for V (its error reaches the output directly).
    gemm_nt<false><<<ggrid, 256>>>(x, Wq, q, ROWS_TOT, CDIM, CDIM);
    gemm_nt<false><<<ggrid, 256>>>(x, Wk, k, ROWS_TOT, CDIM, CDIM);
    gemm_nt<true ><<<ggrid, 256>>>(x, Wv, v, ROWS_TOT, CDIM, CDIM);

    scores_kernel<<<dim3(TSEQ / 64, TSEQ / 64, NBH), 128>>>();
    softmax_kernel<<<NBH * TSEQ, 128>>>();
    pv_kernel<<<dim3(TSEQ / 64, NBH), 128>>>();

    // Output projection: split-tf32 (errors here hit the output 1:1).
    gemm_nt<true ><<<ggrid, 256>>>(o, Wo, out, ROWS_TOT, CDIM, CDIM);
}

// round 2
// speedup vs baseline: 1.5375x; 1.5375x over previous
#include <cuda_runtime.h>
#include <cstdint>
#include <cstddef>

// Problem constants
#define TSEQ   2048
#define CDIM   1024
#define NBATCH 2
#define NHEAD  16
#define HDIM   64
#define NBH    (NBATCH * NHEAD)       // 32
#define ROWS_TOT (NBATCH * TSEQ)      // 4096
#define QK_SCALE 0.125f               // 1/sqrt(64)

// ---------------------------------------------------------------------------
// Scratch (device globals: the sanctioned allocation-free scratch mechanism)
// ---------------------------------------------------------------------------
__device__ float g_q[(size_t)ROWS_TOT * CDIM];           // 16 MB
__device__ float g_k[(size_t)ROWS_TOT * CDIM];           // 16 MB
__device__ float g_v[(size_t)ROWS_TOT * CDIM];           // 16 MB
__device__ float g_o[(size_t)ROWS_TOT * CDIM];           // 16 MB

// ---------------------------------------------------------------------------
// Helpers
// ---------------------------------------------------------------------------
__device__ __forceinline__ float tf32r(float x) {
    unsigned u;
    asm("cvt.rna.tf32.f32 %0, %1;" : "=r"(u) : "f"(x));
    return __uint_as_float(u);
}

// m16n8k8 tf32 MMA, fp32 accumulate. Standard fragment layout:
//  A: a0(r=g,c=t) a1(r=g+8,c=t) a2(r=g,c=t+4) a3(r=g+8,c=t+4)
//  B: b0(k=t,n=g) b1(k=t+4,n=g)
//  C: c0(r=g,c=2t) c1(..2t+1) c2(r=g+8,c=2t) c3(..2t+1)     [g=lane>>2, t=lane&3]
__device__ __forceinline__ void mma8(float* c,
    unsigned a0, unsigned a1, unsigned a2, unsigned a3,
    unsigned b0, unsigned b1)
{
    asm volatile(
        "mma.sync.aligned.m16n8k8.row.col.f32.tf32.tf32.f32 "
        "{%0,%1,%2,%3},{%4,%5,%6,%7},{%8,%9},{%0,%1,%2,%3};\n"
        : "+f"(c[0]), "+f"(c[1]), "+f"(c[2]), "+f"(c[3])
        : "r"(a0), "r"(a1), "r"(a2), "r"(a3), "r"(b0), "r"(b1));
}

// ---------------------------------------------------------------------------
// NT GEMM: C[M,N] = A[M,K] * B[N,K]^T   (both row-major, K contiguous)
// Block tile 128x64, 8 warps (4 M x 2 N), warp tile 32x32, K-tile 16.
// SPLIT=true: 2-term tf32 split (3 MMAs) for near-fp32 accuracy.
// ---------------------------------------------------------------------------
template <bool SPLIT>
__global__ void __launch_bounds__(256)
gemm_nt(const float* __restrict__ A, const float* __restrict__ B,
        float* __restrict__ C, int M, int N, int K)
{
    __shared__ float Ah[128][20];
    __shared__ float Bh[64][20];
    __shared__ float Al[SPLIT ? 128 : 1][20];
    __shared__ float Bl[SPLIT ? 64 : 1][20];

    const int t    = threadIdx.x;
    const int bm   = blockIdx.y * 128;
    const int bn   = blockIdx.x * 64;
    const int w    = t >> 5;
    const int lane = t & 31;
    const int g    = lane >> 2;
    const int tg   = lane & 3;
    const int wm   = w & 3;   // 0..3  (M direction)
    const int wn   = w >> 2;  // 0..1  (N direction)

    float acc[2][4][4];
    #pragma unroll
    for (int mt = 0; mt < 2; mt++)
        #pragma unroll
        for (int nt = 0; nt < 4; nt++)
            #pragma unroll
            for (int r = 0; r < 4; r++)
                acc[mt][nt][r] = 0.f;

    for (int kt = 0; kt < K; kt += 16) {
        // Stage A tile (128 x 16) with tf32 split conversion
        #pragma unroll
        for (int i = 0; i < 2; i++) {
            int idx = t + i * 256;          // float4 index, 0..511
            int r   = idx >> 2;
            int c   = (idx & 3) * 4;
            float4 va = *(const float4*)(A + (size_t)(bm + r) * K + kt + c);
            float h0 = tf32r(va.x), h1 = tf32r(va.y), h2 = tf32r(va.z), h3 = tf32r(va.w);
            *(float4*)&Ah[r][c] = make_float4(h0, h1, h2, h3);
            if (SPLIT)
                *(float4*)&Al[r][c] = make_float4(tf32r(va.x - h0), tf32r(va.y - h1),
                                                  tf32r(va.z - h2), tf32r(va.w - h3));
        }
        // Stage B tile (64 x 16)
        {
            int r = t >> 2;
            int c = (t & 3) * 4;
            float4 vb = *(const float4*)(B + (size_t)(bn + r) * K + kt + c);
            float h0 = tf32r(vb.x), h1 = tf32r(vb.y), h2 = tf32r(vb.z), h3 = tf32r(vb.w);
            *(float4*)&Bh[r][c] = make_float4(h0, h1, h2, h3);
            if (SPLIT)
                *(float4*)&Bl[r][c] = make_float4(tf32r(vb.x - h0), tf32r(vb.y - h1),
                                                  tf32r(vb.z - h2), tf32r(vb.w - h3));
        }
        __syncthreads();

        #pragma unroll
        for (int ks = 0; ks < 2; ks++) {
            const int k0 = ks * 8;
            unsigned a0[2], a1[2], a2[2], a3[2];
            unsigned p0[2], p1[2], p2[2], p3[2];
            #pragma unroll
            for (int mt = 0; mt < 2; mt++) {
                int r = wm * 32 + mt * 16 + g;
                a0[mt] = __float_as_uint(Ah[r    ][k0 + tg    ]);
                a1[mt] = __float_as_uint(Ah[r + 8][k0 + tg    ]);
                a2[mt] = __float_as_uint(Ah[r    ][k0 + tg + 4]);
                a3[mt] = __float_as_uint(Ah[r + 8][k0 + tg + 4]);
                if (SPLIT) {
                    p0[mt] = __float_as_uint(Al[r    ][k0 + tg    ]);
                    p1[mt] = __float_as_uint(Al[r + 8][k0 + tg    ]);
                    p2[mt] = __float_as_uint(Al[r    ][k0 + tg + 4]);
                    p3[mt] = __float_as_uint(Al[r + 8][k0 + tg + 4]);
                }
            }
            #pragma unroll
            for (int nt = 0; nt < 4; nt++) {
                int cn = wn * 32 + nt * 8 + g;
                unsigned b0 = __float_as_uint(Bh[cn][k0 + tg    ]);
                unsigned b1 = __float_as_uint(Bh[cn][k0 + tg + 4]);
                unsigned q0 = 0, q1 = 0;
                if (SPLIT) {
                    q0 = __float_as_uint(Bl[cn][k0 + tg    ]);
                    q1 = __float_as_uint(Bl[cn][k0 + tg + 4]);
                }
                #pragma unroll
                for (int mt = 0; mt < 2; mt++) {
                    mma8(acc[mt][nt], a0[mt], a1[mt], a2[mt], a3[mt], b0, b1);
                    if (SPLIT) {
                        mma8(acc[mt][nt], p0[mt], p1[mt], p2[mt], p3[mt], b0, b1);
                        mma8(acc[mt][nt], a0[mt], a1[mt], a2[mt], a3[mt], q0, q1);
                    }
                }
            }
        }
        __syncthreads();
    }

    #pragma unroll
    for (int mt = 0; mt < 2; mt++) {
        #pragma unroll
        for (int nt = 0; nt < 4; nt++) {
            int r = bm + wm * 32 + mt * 16 + g;
            int c = bn + wn * 32 + nt * 8 + 2 * tg;
            C[(size_t)r * N + c]           = acc[mt][nt][0];
            C[(size_t)r * N + c + 1]       = acc[mt][nt][1];
            C[(size_t)(r + 8) * N + c]     = acc[mt][nt][2];
            C[(size_t)(r + 8) * N + c + 1] = acc[mt][nt][3];
        }
    }
}

// ---------------------------------------------------------------------------
// Fused flash attention: for each (b,h, 64-row q tile), loop over k tiles,
// online softmax in registers.
//   - Q A-fragments register-resident for the whole loop.
//   - K/V staged to shared with stride-68 rows => all fragment LDS conflict-free.
//   - S C-fragment is reused directly as the PV A-fragment (no P movement):
//     A_eff[r][k] = P[r][sigma(k)], sigma(k)=2k (k<4), 2(k-4)+1 (k>=4),
//     so the V B-fragment reads rows 8ks+2tg and 8ks+2tg+1.
// 4 warps, each owns 16 q rows. Block = 128 threads.
// ---------------------------------------------------------------------------
__global__ void __launch_bounds__(128) flash_kernel()
{
    const int it = (int)gridDim.x - 1 - (int)blockIdx.x;  // heavy tiles first
    const int bh = blockIdx.y;
    const int b  = bh >> 4, h = bh & 15;

    __shared__ float Ks[64 * 68];
    __shared__ float Vs[64 * 68];

    const int t = threadIdx.x, w = t >> 5, lane = t & 31;
    const int g = lane >> 2, tg = lane & 3;

    // ---- Preload Q A-fragments (scaled + tf32), one-time ----
    unsigned qa[8][4];
    {
        const float* q0 = g_q + (size_t)(b * TSEQ + it * 64 + w * 16 + g) * CDIM + h * 64;
        const float* q8 = q0 + (size_t)8 * CDIM;
        #pragma unroll
        for (int ks = 0; ks < 8; ks++) {
            int c = ks * 8 + tg;
            qa[ks][0] = __float_as_uint(tf32r(q0[c]     * QK_SCALE));
            qa[ks][1] = __float_as_uint(tf32r(q8[c]     * QK_SCALE));
            qa[ks][2] = __float_as_uint(tf32r(q0[c + 4] * QK_SCALE));
            qa[ks][3] = __float_as_uint(tf32r(q8[c + 4] * QK_SCALE));
        }
    }

    float o[8][4];
    #pragma unroll
    for (int nt = 0; nt < 8; nt++)
        #pragma unroll
        for (int r = 0; r < 4; r++) o[nt][r] = 0.f;
    float mA = -1e30f, mB = -1e30f, sA = 0.f, sB = 0.f;

    const float* kbase = g_k + (size_t)(b * TSEQ) * CDIM + h * 64;
    const float* vbase = g_v + (size_t)(b * TSEQ) * CDIM + h * 64;
    const int rA = w * 16 + g;      // local q row (first half)
    const int rB = rA + 8;

    for (int jt = 0; jt <= it; jt++) {
        // ---- Stage K and V tiles (64x64) into stride-68 shared ----
        #pragma unroll
        for (int u = 0; u < 8; u++) {
            int unit = t + u * 128;           // 0..1023 float4 units
            int r    = unit >> 4;
            int c    = (unit & 15) * 4;
            size_t goff = (size_t)(jt * 64 + r) * CDIM + c;
            float4 k4 = *(const float4*)(kbase + goff);
            *(float4*)&Ks[r * 68 + c] =
                make_float4(tf32r(k4.x), tf32r(k4.y), tf32r(k4.z), tf32r(k4.w));
            float4 v4 = *(const float4*)(vbase + goff);
            *(float4*)&Vs[r * 68 + c] =
                make_float4(tf32r(v4.x), tf32r(v4.y), tf32r(v4.z), tf32r(v4.w));
        }
        __syncthreads();

        // ---- S = Q K^T ----
        float s[8][4];
        #pragma unroll
        for (int nt = 0; nt < 8; nt++)
            #pragma unroll
            for (int r = 0; r < 4; r++) s[nt][r] = 0.f;

        #pragma unroll
        for (int ks = 0; ks < 8; ks++) {
            #pragma unroll
            for (int nt = 0; nt < 8; nt++) {
                int n = nt * 8 + g;
                unsigned b0 = __float_as_uint(Ks[n * 68 + ks * 8 + tg]);
                unsigned b1 = __float_as_uint(Ks[n * 68 + ks * 8 + tg + 4]);
                mma8(s[nt], qa[ks][0], qa[ks][1], qa[ks][2], qa[ks][3], b0, b1);
            }
        }

        // ---- Causal mask on the diagonal tile ----
        if (jt == it) {
            #pragma unroll
            for (int nt = 0; nt < 8; nt++) {
                int c0 = nt * 8 + 2 * tg, c1 = c0 + 1;
                if (c0 > rA) s[nt][0] = -1e30f;
                if (c1 > rA) s[nt][1] = -1e30f;
                if (c0 > rB) s[nt][2] = -1e30f;
                if (c1 > rB) s[nt][3] = -1e30f;
            }
        }

        // ---- Online softmax (per-row; rows live in fixed lanes, quad-reduce) ----
        float tmA = -1e30f, tmB = -1e30f;
        #pragma unroll
        for (int nt = 0; nt < 8; nt++) {
            tmA = fmaxf(tmA, fmaxf(s[nt][0], s[nt][1]));
            tmB = fmaxf(tmB, fmaxf(s[nt][2], s[nt][3]));
        }
        tmA = fmaxf(tmA, __shfl_xor_sync(0xffffffffu, tmA, 1));
        tmA = fmaxf(tmA, __shfl_xor_sync(0xffffffffu, tmA, 2));
        tmB = fmaxf(tmB, __shfl_xor_sync(0xffffffffu, tmB, 1));
        tmB = fmaxf(tmB, __shfl_xor_sync(0xffffffffu, tmB, 2));

        float nmA = fmaxf(mA, tmA), nmB = fmaxf(mB, tmB);
        float aA = __expf(mA - nmA), aB = __expf(mB - nmB);
        mA = nmA; mB = nmB;

        float psA = 0.f, psB = 0.f;
        #pragma unroll
        for (int nt = 0; nt < 8; nt++) {
            float p0 = tf32r(__expf(s[nt][0] - nmA));
            float p1 = tf32r(__expf(s[nt][1] - nmA));
            float p2 = tf32r(__expf(s[nt][2] - nmB));
            float p3 = tf32r(__expf(s[nt][3] - nmB));
            s[nt][0] = p0; s[nt][1] = p1; s[nt][2] = p2; s[nt][3] = p3;
            psA += p0 + p1;
            psB += p2 + p3;
        }
        sA = sA * aA + psA;
        sB = sB * aB + psB;
        #pragma unroll
        for (int nt = 0; nt < 8; nt++) {
            o[nt][0] *= aA; o[nt][1] *= aA;
            o[nt][2] *= aB; o[nt][3] *= aB;
        }

        // ---- O += P V  (S fragment reused as A; V rows permuted via sigma) ----
        #pragma unroll
        for (int ks = 0; ks < 8; ks++) {
            unsigned a0 = __float_as_uint(s[ks][0]);
            unsigned a1 = __float_as_uint(s[ks][2]);
            unsigned a2 = __float_as_uint(s[ks][1]);
            unsigned a3 = __float_as_uint(s[ks][3]);
            #pragma unroll
            for (int nt = 0; nt < 8; nt++) {
                int n = nt * 8 + g;
                unsigned b0 = __float_as_uint(Vs[(ks * 8 + 2 * tg)     * 68 + n]);
                unsigned b1 = __float_as_uint(Vs[(ks * 8 + 2 * tg + 1) * 68 + n]);
                mma8(o[nt], a0, a1, a2, a3, b0, b1);
            }
        }
        __syncthreads();
    }

    // ---- Normalize and write ----
    sA += __shfl_xor_sync(0xffffffffu, sA, 1);
    sA += __shfl_xor_sync(0xffffffffu, sA, 2);
    sB += __shfl_xor_sync(0xffffffffu, sB, 1);
    sB += __shfl_xor_sync(0xffffffffu, sB, 2);
    const float iA = 1.f / sA, iB = 1.f / sB;

    float* ob = g_o + (size_t)(b * TSEQ + it * 64 + rA) * CDIM + h * 64;
    #pragma unroll
    for (int nt = 0; nt < 8; nt++) {
        int c = nt * 8 + 2 * tg;
        *(float2*)(ob + c)                    = make_float2(o[nt][0] * iA, o[nt][1] * iA);
        *(float2*)(ob + (size_t)8 * CDIM + c) = make_float2(o[nt][2] * iB, o[nt][3] * iB);
    }
}

// ---------------------------------------------------------------------------
// Launch
// ---------------------------------------------------------------------------
extern "C" void kernel_launch(void* const* d_in, const int* in_sizes, int n_in,
                              void* d_out, int out_size)
{
    const float* x  = (const float*)d_in[0];
    const float* Wq = (const float*)d_in[1];
    const float* Wk = (const float*)d_in[2];
    const float* Wv = (const float*)d_in[3];
    const float* Wo = (const float*)d_in[4];
    float* out = (float*)d_out;

    float *q, *k, *v, *o;
    cudaGetSymbolAddress((void**)&q, g_q);
    cudaGetSymbolAddress((void**)&k, g_k);
    cudaGetSymbolAddress((void**)&v, g_v);
    cudaGetSymbolAddress((void**)&o, g_o);

    dim3 ggrid(CDIM / 64, ROWS_TOT / 128);   // (16, 32)

    // Projections: plain tf32 (softmax / averaging tolerate ~3e-4 stage error).
    gemm_nt<false><<<ggrid, 256>>>(x, Wq, q, ROWS_TOT, CDIM, CDIM);
    gemm_nt<false><<<ggrid, 256>>>(x, Wk, k, ROWS_TOT, CDIM, CDIM);
    gemm_nt<false><<<ggrid, 256>>>(x, Wv, v, ROWS_TOT, CDIM, CDIM);

    // Fused attention (scores + softmax + PV)
    flash_kernel<<<dim3(TSEQ / 64, NBH), 128>>>();

    // Output projection: split-tf32 (errors here hit the output 1:1).
    gemm_nt<true><<<ggrid, 256>>>(o, Wo, out, ROWS_TOT, CDIM, CDIM);
}

// round 3
// speedup vs baseline: 1.5412x; 1.0024x over previous
#include <cuda_runtime.h>
#include <cstdint>
#include <cstddef>

// Problem constants
#define TSEQ   2048
#define CDIM   1024
#define NBATCH 2
#define NHEAD  16
#define HDIM   64
#define NBH    (NBATCH * NHEAD)       // 32
#define ROWS_TOT (NBATCH * TSEQ)      // 4096
#define QK_SCALE 0.125f               // 1/sqrt(64)

// ---------------------------------------------------------------------------
// Scratch (device globals: the sanctioned allocation-free scratch mechanism)
// ---------------------------------------------------------------------------
__device__ float g_q[(size_t)ROWS_TOT * CDIM];           // 16 MB
__device__ float g_k[(size_t)ROWS_TOT * CDIM];           // 16 MB
__device__ float g_v[(size_t)ROWS_TOT * CDIM];           // 16 MB
__device__ float g_o[(size_t)ROWS_TOT * CDIM];           // 16 MB

// ---------------------------------------------------------------------------
// Helpers
// ---------------------------------------------------------------------------
__device__ __forceinline__ float tf32r(float x) {
    unsigned u;
    asm("cvt.rna.tf32.f32 %0, %1;" : "=r"(u) : "f"(x));
    return __uint_as_float(u);
}

// m16n8k8 tf32 MMA, fp32 accumulate. Standard fragment layout:
//  A: a0(r=g,c=t) a1(r=g+8,c=t) a2(r=g,c=t+4) a3(r=g+8,c=t+4)
//  B: b0(k=t,n=g) b1(k=t+4,n=g)
//  C: c0(r=g,c=2t) c1(..2t+1) c2(r=g+8,c=2t) c3(..2t+1)     [g=lane>>2, t=lane&3]
__device__ __forceinline__ void mma8(float* c,
    unsigned a0, unsigned a1, unsigned a2, unsigned a3,
    unsigned b0, unsigned b1)
{
    asm volatile(
        "mma.sync.aligned.m16n8k8.row.col.f32.tf32.tf32.f32 "
        "{%0,%1,%2,%3},{%4,%5,%6,%7},{%8,%9},{%0,%1,%2,%3};\n"
        : "+f"(c[0]), "+f"(c[1]), "+f"(c[2]), "+f"(c[3])
        : "r"(a0), "r"(a1), "r"(a2), "r"(a3), "r"(b0), "r"(b1));
}

// ---------------------------------------------------------------------------
// NT GEMM: C[M,N] = A[M,K] * B[N,K]^T   (both row-major, K contiguous)
// Block tile 128x64, 8 warps (4 M x 2 N), warp tile 32x32, K-tile 16.
// SPLIT=true: 2-term tf32 split (3 MMAs) for near-fp32 accuracy.
// ---------------------------------------------------------------------------
template <bool SPLIT>
__global__ void __launch_bounds__(256)
gemm_nt(const float* __restrict__ A, const float* __restrict__ B,
        float* __restrict__ C, int M, int N, int K)
{
    __shared__ float Ah[128][20];
    __shared__ float Bh[64][20];
    __shared__ float Al[SPLIT ? 128 : 1][20];
    __shared__ float Bl[SPLIT ? 64 : 1][20];

    const int t    = threadIdx.x;
    const int bm   = blockIdx.y * 128;
    const int bn   = blockIdx.x * 64;
    const int w    = t >> 5;
    const int lane = t & 31;
    const int g    = lane >> 2;
    const int tg   = lane & 3;
    const int wm   = w & 3;   // 0..3  (M direction)
    const int wn   = w >> 2;  // 0..1  (N direction)

    float acc[2][4][4];
    #pragma unroll
    for (int mt = 0; mt < 2; mt++)
        #pragma unroll
        for (int nt = 0; nt < 4; nt++)
            #pragma unroll
            for (int r = 0; r < 4; r++)
                acc[mt][nt][r] = 0.f;

    for (int kt = 0; kt < K; kt += 16) {
        // Stage A tile (128 x 16) with tf32 split conversion
        #pragma unroll
        for (int i = 0; i < 2; i++) {
            int idx = t + i * 256;          // float4 index, 0..511
            int r   = idx >> 2;
            int c   = (idx & 3) * 4;
            float4 va = *(const float4*)(A + (size_t)(bm + r) * K + kt + c);
            float h0 = tf32r(va.x), h1 = tf32r(va.y), h2 = tf32r(va.z), h3 = tf32r(va.w);
            *(float4*)&Ah[r][c] = make_float4(h0, h1, h2, h3);
            if (SPLIT)
                *(float4*)&Al[r][c] = make_float4(tf32r(va.x - h0), tf32r(va.y - h1),
                                                  tf32r(va.z - h2), tf32r(va.w - h3));
        }
        // Stage B tile (64 x 16)
        {
            int r = t >> 2;
            int c = (t & 3) * 4;
            float4 vb = *(const float4*)(B + (size_t)(bn + r) * K + kt + c);
            float h0 = tf32r(vb.x), h1 = tf32r(vb.y), h2 = tf32r(vb.z), h3 = tf32r(vb.w);
            *(float4*)&Bh[r][c] = make_float4(h0, h1, h2, h3);
            if (SPLIT)
                *(float4*)&Bl[r][c] = make_float4(tf32r(vb.x - h0), tf32r(vb.y - h1),
                                                  tf32r(vb.z - h2), tf32r(vb.w - h3));
        }
        __syncthreads();

        #pragma unroll
        for (int ks = 0; ks < 2; ks++) {
            const int k0 = ks * 8;
            unsigned a0[2], a1[2], a2[2], a3[2];
            unsigned p0[2], p1[2], p2[2], p3[2];
            #pragma unroll
            for (int mt = 0; mt < 2; mt++) {
                int r = wm * 32 + mt * 16 + g;
                a0[mt] = __float_as_uint(Ah[r    ][k0 + tg    ]);
                a1[mt] = __float_as_uint(Ah[r + 8][k0 + tg    ]);
                a2[mt] = __float_as_uint(Ah[r    ][k0 + tg + 4]);
                a3[mt] = __float_as_uint(Ah[r + 8][k0 + tg + 4]);
                if (SPLIT) {
                    p0[mt] = __float_as_uint(Al[r    ][k0 + tg    ]);
                    p1[mt] = __float_as_uint(Al[r + 8][k0 + tg    ]);
                    p2[mt] = __float_as_uint(Al[r    ][k0 + tg + 4]);
                    p3[mt] = __float_as_uint(Al[r + 8][k0 + tg + 4]);
                }
            }
            #pragma unroll
            for (int nt = 0; nt < 4; nt++) {
                int cn = wn * 32 + nt * 8 + g;
                unsigned b0 = __float_as_uint(Bh[cn][k0 + tg    ]);
                unsigned b1 = __float_as_uint(Bh[cn][k0 + tg + 4]);
                unsigned q0 = 0, q1 = 0;
                if (SPLIT) {
                    q0 = __float_as_uint(Bl[cn][k0 + tg    ]);
                    q1 = __float_as_uint(Bl[cn][k0 + tg + 4]);
                }
                #pragma unroll
                for (int mt = 0; mt < 2; mt++) {
                    mma8(acc[mt][nt], a0[mt], a1[mt], a2[mt], a3[mt], b0, b1);
                    if (SPLIT) {
                        mma8(acc[mt][nt], p0[mt], p1[mt], p2[mt], p3[mt], b0, b1);
                        mma8(acc[mt][nt], a0[mt], a1[mt], a2[mt], a3[mt], q0, q1);
                    }
                }
            }
        }
        __syncthreads();
    }

    #pragma unroll
    for (int mt = 0; mt < 2; mt++) {
        #pragma unroll
        for (int nt = 0; nt < 4; nt++) {
            int r = bm + wm * 32 + mt * 16 + g;
            int c = bn + wn * 32 + nt * 8 + 2 * tg;
            C[(size_t)r * N + c]           = acc[mt][nt][0];
            C[(size_t)r * N + c + 1]       = acc[mt][nt][1];
            C[(size_t)(r + 8) * N + c]     = acc[mt][nt][2];
            C[(size_t)(r + 8) * N + c + 1] = acc[mt][nt][3];
        }
    }
}

// ---------------------------------------------------------------------------
// Fused flash attention: for each (b,h, 64-row q tile), loop over k tiles,
// online softmax in registers.
//   - Q A-fragments register-resident for the whole loop.
//   - K/V staged to shared with stride-68 rows => all fragment LDS conflict-free.
//   - S C-fragment is reused directly as the PV A-fragment (no P movement):
//     A_eff[r][k] = P[r][sigma(k)], sigma(k)=2k (k<4), 2(k-4)+1 (k>=4),
//     so the V B-fragment reads rows 8ks+2tg and 8ks+2tg+1.
// 4 warps, each owns 16 q rows. Block = 128 threads.
// ---------------------------------------------------------------------------
__global__ void __launch_bounds__(128) flash_kernel()
{
    const int it = (int)gridDim.x - 1 - (int)blockIdx.x;  // heavy tiles first
    const int bh = blockIdx.y;
    const int b  = bh >> 4, h = bh & 15;

    __shared__ float Ks[64 * 68];
    __shared__ float Vs[64 * 68];

    const int t = threadIdx.x, w = t >> 5, lane = t & 31;
    const int g = lane >> 2, tg = lane & 3;

    // ---- Preload Q A-fragments (scaled + tf32), one-time ----
    unsigned qa[8][4];
    {
        const float* q0 = g_q + (size_t)(b * TSEQ + it * 64 + w * 16 + g) * CDIM + h * 64;
        const float* q8 = q0 + (size_t)8 * CDIM;
        #pragma unroll
        for (int ks = 0; ks < 8; ks++) {
            int c = ks * 8 + tg;
            qa[ks][0] = __float_as_uint(tf32r(q0[c]     * QK_SCALE));
            qa[ks][1] = __float_as_uint(tf32r(q8[c]     * QK_SCALE));
            qa[ks][2] = __float_as_uint(tf32r(q0[c + 4] * QK_SCALE));
            qa[ks][3] = __float_as_uint(tf32r(q8[c + 4] * QK_SCALE));
        }
    }

    float o[8][4];
    #pragma unroll
    for (int nt = 0; nt < 8; nt++)
        #pragma unroll
        for (int r = 0; r < 4; r++) o[nt][r] = 0.f;
    float mA = -1e30f, mB = -1e30f, sA = 0.f, sB = 0.f;

    const float* kbase = g_k + (size_t)(b * TSEQ) * CDIM + h * 64;
    const float* vbase = g_v + (size_t)(b * TSEQ) * CDIM + h * 64;
    const int rA = w * 16 + g;      // local q row (first half)
    const int rB = rA + 8;

    for (int jt = 0; jt <= it; jt++) {
        // ---- Stage K and V tiles (64x64) into stride-68 shared ----
        #pragma unroll
        for (int u = 0; u < 8; u++) {
            int unit = t + u * 128;           // 0..1023 float4 units
            int r    = unit >> 4;
            int c    = (unit & 15) * 4;
            size_t goff = (size_t)(jt * 64 + r) * CDIM + c;
            float4 k4 = *(const float4*)(kbase + goff);
            *(float4*)&Ks[r * 68 + c] =
                make_float4(tf32r(k4.x), tf32r(k4.y), tf32r(k4.z), tf32r(k4.w));
            float4 v4 = *(const float4*)(vbase + goff);
            *(float4*)&Vs[r * 68 + c] =
                make_float4(tf32r(v4.x), tf32r(v4.y), tf32r(v4.z), tf32r(v4.w));
        }
        __syncthreads();

        // ---- S = Q K^T ----
        float s[8][4];
        #pragma unroll
        for (int nt = 0; nt < 8; nt++)
            #pragma unroll
            for (int r = 0; r < 4; r++) s[nt][r] = 0.f;

        #pragma unroll
        for (int ks = 0; ks < 8; ks++) {
            #pragma unroll
            for (int nt = 0; nt < 8; nt++) {
                int n = nt * 8 + g;
                unsigned b0 = __float_as_uint(Ks[n * 68 + ks * 8 + tg]);
                unsigned b1 = __float_as_uint(Ks[n * 68 + ks * 8 + tg + 4]);
                mma8(s[nt], qa[ks][0], qa[ks][1], qa[ks][2], qa[ks][3], b0, b1);
            }
        }

        // ---- Causal mask on the diagonal tile ----
        if (jt == it) {
            #pragma unroll
            for (int nt = 0; nt < 8; nt++) {
                int c0 = nt * 8 + 2 * tg, c1 = c0 + 1;
                if (c0 > rA) s[nt][0] = -1e30f;
                if (c1 > rA) s[nt][1] = -1e30f;
                if (c0 > rB) s[nt][2] = -1e30f;
                if (c1 > rB) s[nt][3] = -1e30f;
            }
        }

        // ---- Online softmax (per-row; rows live in fixed lanes, quad-reduce) ----
        float tmA = -1e30f, tmB = -1e30f;
        #pragma unroll
        for (int nt = 0; nt < 8; nt++) {
            tmA = fmaxf(tmA, fmaxf(s[nt][0], s[nt][1]));
            tmB = fmaxf(tmB, fmaxf(s[nt][2], s[nt][3]));
        }
        tmA = fmaxf(tmA, __shfl_xor_sync(0xffffffffu, tmA, 1));
        tmA = fmaxf(tmA, __shfl_xor_sync(0xffffffffu, tmA, 2));
        tmB = fmaxf(tmB, __shfl_xor_sync(0xffffffffu, tmB, 1));
        tmB = fmaxf(tmB, __shfl_xor_sync(0xffffffffu, tmB, 2));

        float nmA = fmaxf(mA, tmA), nmB = fmaxf(mB, tmB);
        float aA = __expf(mA - nmA), aB = __expf(mB - nmB);
        mA = nmA; mB = nmB;

        float psA = 0.f, psB = 0.f;
        #pragma unroll
        for (int nt = 0; nt < 8; nt++) {
            float p0 = tf32r(__expf(s[nt][0] - nmA));
            float p1 = tf32r(__expf(s[nt][1] - nmA));
            float p2 = tf32r(__expf(s[nt][2] - nmB));
            float p3 = tf32r(__expf(s[nt][3] - nmB));
            s[nt][0] = p0; s[nt][1] = p1; s[nt][2] = p2; s[nt][3] = p3;
            psA += p0 + p1;
            psB += p2 + p3;
        }
        sA = sA * aA + psA;
        sB = sB * aB + psB;
        #pragma unroll
        for (int nt = 0; nt < 8; nt++) {
            o[nt][0] *= aA; o[nt][1] *= aA;
            o[nt][2] *= aB; o[nt][3] *= aB;
        }

        // ---- O += P V  (S fragment reused as A; V rows permuted via sigma) ----
        #pragma unroll
        for (int ks = 0; ks < 8; ks++) {
            unsigned a0 = __float_as_uint(s[ks][0]);
            unsigned a1 = __float_as_uint(s[ks][2]);
            unsigned a2 = __float_as_uint(s[ks][1]);
            unsigned a3 = __float_as_uint(s[ks][3]);
            #pragma unroll
            for (int nt = 0; nt < 8; nt++) {
                int n = nt * 8 + g;
                unsigned b0 = __float_as_uint(Vs[(ks * 8 + 2 * tg)     * 68 + n]);
                unsigned b1 = __float_as_uint(Vs[(ks * 8 + 2 * tg + 1) * 68 + n]);
                mma8(o[nt], a0, a1, a2, a3, b0, b1);
            }
        }
        __syncthreads();
    }

    // ---- Normalize and write ----
    sA += __shfl_xor_sync(0xffffffffu, sA, 1);
    sA += __shfl_xor_sync(0xffffffffu, sA, 2);
    sB += __shfl_xor_sync(0xffffffffu, sB, 1);
    sB += __shfl_xor_sync(0xffffffffu, sB, 2);
    const float iA = 1.f / sA, iB = 1.f / sB;

    float* ob = g_o + (size_t)(b * TSEQ + it * 64 + rA) * CDIM + h * 64;
    #pragma unroll
    for (int nt = 0; nt < 8; nt++) {
        int c = nt * 8 + 2 * tg;
        *(float2*)(ob + c)                    = make_float2(o[nt][0] * iA, o[nt][1] * iA);
        *(float2*)(ob + (size_t)8 * CDIM + c) = make_float2(o[nt][2] * iB, o[nt][3] * iB);
    }
}

// ---------------------------------------------------------------------------
// Launch
// ---------------------------------------------------------------------------
extern "C" void kernel_launch(void* const* d_in, const int* in_sizes, int n_in,
                              void* d_out, int out_size)
{
    const float* x  = (const float*)d_in[0];
    const float* Wq = (const float*)d_in[1];
    const float* Wk = (const float*)d_in[2];
    const float* Wv = (const float*)d_in[3];
    const float* Wo = (const float*)d_in[4];
    float* out = (float*)d_out;

    float *q, *k, *v, *o;
    cudaGetSymbolAddress((void**)&q, g_q);
    cudaGetSymbolAddress((void**)&k, g_k);
    cudaGetSymbolAddress((void**)&v, g_v);
    cudaGetSymbolAddress((void**)&o, g_o);

    dim3 ggrid(CDIM / 64, ROWS_TOT / 128);   // (16, 32)

    // Projections: plain tf32 (softmax / averaging tolerate ~3e-4 stage error).
    gemm_nt<false><<<ggrid, 256>>>(x, Wq, q, ROWS_TOT, CDIM, CDIM);
    gemm_nt<false><<<ggrid, 256>>>(x, Wk, k, ROWS_TOT, CDIM, CDIM);
    gemm_nt<false><<<ggrid, 256>>>(x, Wv, v, ROWS_TOT, CDIM, CDIM);

    // Fused attention (scores + softmax + PV)
    flash_kernel<<<dim3(TSEQ / 64, NBH), 128>>>();

    // Output projection: split-tf32 (errors here hit the output 1:1).
    gemm_nt<true><<<ggrid, 256>>>(o, Wo, out, ROWS_TOT, CDIM, CDIM);
}